// round 9
// baseline (speedup 1.0000x reference)
#include <cuda_runtime.h>
#include <cuda_bf16.h>
#include <math.h>
#include <stdint.h>

// Shapes: B=4, N=256, F=64, H=256, A=16, T=3
#define Bn 4
#define Nn 256
#define Fn 64
#define Hn 256
#define An 16
#define Tn 3
#define BN 1024
#define NC 1280

typedef unsigned long long u64;

// ---------------- scratch (device globals) -----------------------------------
__device__ float d_XT  [Fn*BN];      // X^T        [64][1024]
__device__ float d_tT  [Hn*BN];      // pre-hidden^T
__device__ float d_hT  [Hn*BN];      // h^T
__device__ float d_aT  [Hn*BN];      // agg0^T
__device__ float d_M2T [Hn*Hn];      // msg_W2^T
__device__ float d_big2[BN*512];     // [hi+b1 | hj] row-major
__device__ float d_ghT [768*BN];     // gh^T (+bhh)
__device__ float d_deg [BN];
__device__ float d_Wc  [Hn*768];     // msg_W2 @ gru_Wih (row-major)
__device__ float d_bc  [768];        // msg_b2 @ gru_Wih
__device__ float d_Wcat[Hn*NC];      // [W1_i | W1_j | Whh] row-major
__device__ float d_bcat[NC];

// ---------------- helpers ------------------------------------------------------
#define FMA2(acc, a, b) \
    asm("fma.rn.f32x2 %0, %1, %2, %0;" : "+l"(acc) : "l"(a), "l"(b))
#define PACKDUP(d, s) \
    asm("mov.b64 %0, {%1, %1};" : "=l"(d) : "f"(s))
#define UNPACK2(lo, hi, s) \
    asm("mov.b64 {%0, %1}, %2;" : "=f"(lo), "=f"(hi) : "l"(s))

__device__ __forceinline__ void cpa16(void* s, const void* g) {
    uint32_t sa = (uint32_t)__cvta_generic_to_shared(s);
    asm volatile("cp.async.ca.shared.global [%0], [%1], 16;" :: "r"(sa), "l"(g));
}

// ---------------- pipelined fp32 GEMM (K-chunks of 32, 3 stages) --------------
// C = f(A@B + bias), A TRANSPOSED At[k][m] (ld ldaT), B row-major KxN.
// Tile 64x64, 128 thr, FFMA2. K multiple of 32 (>=64).
// Block cols < splitCol -> Crow[r][c] (ld ldC); else CtrT[(c-splitCol)][r] (ld ldT).
#define AS_W 68
#define GEMM_SMEM ((3*32*AS_W + 3*32*64) * 4)
__global__ void __launch_bounds__(128)
gemmT(const float* __restrict__ At, int ldaT,
      const float* __restrict__ Bm, int N, int K,
      const float* __restrict__ bias,
      float* __restrict__ Crow, int ldC, int splitCol,
      float* __restrict__ CtrT, int ldT, int doRelu)
{
    extern __shared__ __align__(16) float dsm[];
    float (*As)[32][AS_W] = (float(*)[32][AS_W])dsm;
    float (*Bs)[32][64]   = (float(*)[32][64])(dsm + 3*32*AS_W);

    int tid = threadIdx.x;
    int l = tid & 31, w = tid >> 5;
    int wm = w >> 1, wn = w & 1;
    int rg = l >> 2, cg = l & 3;
    int row0 = blockIdx.y * 64, col0 = blockIdx.x * 64;

    int lk = tid >> 4, lseg = (tid & 15) << 2;
    const float* Abase = At + row0 + lseg;
    const float* Bbase = Bm + col0 + lseg;

    u64 acc[4][4];
    #pragma unroll
    for (int i = 0; i < 4; i++)
        #pragma unroll
        for (int j = 0; j < 4; j++) acc[i][j] = 0ull;

    int nch = K >> 5;
    #pragma unroll
    for (int p = 0; p < 2; p++) {
        int kc = p << 5;
        #pragma unroll
        for (int r = 0; r < 32; r += 8) {
            cpa16(&As[p][lk + r][lseg], Abase + (size_t)(kc + lk + r) * ldaT);
            cpa16(&Bs[p][lk + r][lseg], Bbase + (size_t)(kc + lk + r) * N);
        }
        asm volatile("cp.async.commit_group;");
    }

    int mrow = wm * 32 + rg * 4, nc0 = wn * 32 + cg * 4;
    int s = 0;
    for (int ch = 0; ch < nch; ch++) {
        if (ch < nch - 1) asm volatile("cp.async.wait_group 1;");
        else              asm volatile("cp.async.wait_group 0;");
        __syncthreads();

        if (ch + 2 < nch) {
            int s2 = s + 2; if (s2 >= 3) s2 -= 3;
            int kc = (ch + 2) << 5;
            #pragma unroll
            for (int r = 0; r < 32; r += 8) {
                cpa16(&As[s2][lk + r][lseg], Abase + (size_t)(kc + lk + r) * ldaT);
                cpa16(&Bs[s2][lk + r][lseg], Bbase + (size_t)(kc + lk + r) * N);
            }
            asm volatile("cp.async.commit_group;");
        }

        #pragma unroll
        for (int k = 0; k < 32; k++) {
            float4 av = *(float4*)&As[s][k][mrow];
            ulonglong2 b0 = *(ulonglong2*)&Bs[s][k][nc0];
            ulonglong2 b1 = *(ulonglong2*)&Bs[s][k][nc0 + 16];
            u64 ad0, ad1, ad2, ad3;
            PACKDUP(ad0, av.x); PACKDUP(ad1, av.y); PACKDUP(ad2, av.z); PACKDUP(ad3, av.w);
            FMA2(acc[0][0], ad0, b0.x); FMA2(acc[0][1], ad0, b0.y);
            FMA2(acc[0][2], ad0, b1.x); FMA2(acc[0][3], ad0, b1.y);
            FMA2(acc[1][0], ad1, b0.x); FMA2(acc[1][1], ad1, b0.y);
            FMA2(acc[1][2], ad1, b1.x); FMA2(acc[1][3], ad1, b1.y);
            FMA2(acc[2][0], ad2, b0.x); FMA2(acc[2][1], ad2, b0.y);
            FMA2(acc[2][2], ad2, b1.x); FMA2(acc[2][3], ad2, b1.y);
            FMA2(acc[3][0], ad3, b0.x); FMA2(acc[3][1], ad3, b0.y);
            FMA2(acc[3][2], ad3, b1.x); FMA2(acc[3][3], ad3, b1.y);
        }
        s++; if (s >= 3) s = 0;
    }

    // epilogue
    float vv[4][8];
    #pragma unroll
    for (int i = 0; i < 4; i++) {
        UNPACK2(vv[i][0], vv[i][1], acc[i][0]);
        UNPACK2(vv[i][2], vv[i][3], acc[i][1]);
        UNPACK2(vv[i][4], vv[i][5], acc[i][2]);
        UNPACK2(vv[i][6], vv[i][7], acc[i][3]);
    }
    const int cofs[8] = {0, 1, 2, 3, 16, 17, 18, 19};
    int c0 = col0 + nc0;
    #pragma unroll
    for (int j = 0; j < 8; j++) {
        float bj = bias ? bias[c0 + cofs[j]] : 0.f;
        #pragma unroll
        for (int i = 0; i < 4; i++) {
            float v = vv[i][j] + bj;
            if (doRelu) v = fmaxf(v, 0.f);
            vv[i][j] = v;
        }
    }
    if (col0 < splitCol) {
        #pragma unroll
        for (int i = 0; i < 4; i++) {
            int r = row0 + mrow + i;
            float4 o0 = {vv[i][0], vv[i][1], vv[i][2], vv[i][3]};
            float4 o1 = {vv[i][4], vv[i][5], vv[i][6], vv[i][7]};
            *(float4*)(Crow + (size_t)r * ldC + c0)      = o0;
            *(float4*)(Crow + (size_t)r * ldC + c0 + 16) = o1;
        }
    } else {
        int rbase = row0 + mrow;
        #pragma unroll
        for (int j = 0; j < 8; j++) {
            float4 o = {vv[0][j], vv[1][j], vv[2][j], vv[3][j]};
            *(float4*)(CtrT + (size_t)(c0 + cofs[j] - splitCol) * ldT + rbase) = o;
        }
    }
}

// ---------------- fused gi-GEMM + GRU -----------------------------------------
// Block: 64 rows x 64 h-cols, all 3 gate segments. 256 thr, K-chunks of 16.
// gi[r][c] = (agg0@Wc)[r][seg*256+c] + deg[r]*bc[..] + bih[..]; GRU -> hT.
#define GG_SMEM ((3*16*AS_W + 3*16*192) * 4)
__global__ void __launch_bounds__(256)
gigru(const float* __restrict__ aT,          // [k][m] ld BN
      const float* __restrict__ Wc,          // 256 x 768
      const float* __restrict__ bih, const float* __restrict__ bc,
      const float* __restrict__ deg, const float* __restrict__ ghT,
      float* __restrict__ hT)
{
    extern __shared__ __align__(16) float dsm[];
    float (*As)[16][AS_W] = (float(*)[16][AS_W])dsm;
    float (*Bs)[16][192]  = (float(*)[16][192])(dsm + 3*16*AS_W);

    int tid = threadIdx.x;
    int l = tid & 31, w = tid >> 5;
    int wm = w >> 2, wn = w & 3;          // 2(m) x 4(n)
    int rg = l >> 2, cg = l & 3;
    int g = blockIdx.x;                   // h-col group (64 cols)
    int row0 = blockIdx.y * 64;

    int lk = tid >> 4, lseg = (tid & 15) << 2;
    const float* Abase = aT + row0 + lseg;
    const float* Bbase = Wc + g * 64 + lseg;

    u64 acc[4][3][2];
    #pragma unroll
    for (int i = 0; i < 4; i++)
        #pragma unroll
        for (int sg = 0; sg < 3; sg++) { acc[i][sg][0] = 0ull; acc[i][sg][1] = 0ull; }

    #pragma unroll
    for (int p = 0; p < 2; p++) {
        int kc = p << 4;
        cpa16(&As[p][lk][lseg], Abase + (size_t)(kc + lk) * BN);
        #pragma unroll
        for (int sg = 0; sg < 3; sg++)
            cpa16(&Bs[p][lk][sg * 64 + lseg], Bbase + (size_t)(kc + lk) * 768 + sg * 256);
        asm volatile("cp.async.commit_group;");
    }

    int mrow = wm * 32 + rg * 4, nc0 = wn * 16 + cg * 4;
    int s = 0;
    for (int ch = 0; ch < 16; ch++) {
        if (ch < 15) asm volatile("cp.async.wait_group 1;");
        else         asm volatile("cp.async.wait_group 0;");
        __syncthreads();

        if (ch + 2 < 16) {
            int s2 = s + 2; if (s2 >= 3) s2 -= 3;
            int kc = (ch + 2) << 4;
            cpa16(&As[s2][lk][lseg], Abase + (size_t)(kc + lk) * BN);
            #pragma unroll
            for (int sg = 0; sg < 3; sg++)
                cpa16(&Bs[s2][lk][sg * 64 + lseg], Bbase + (size_t)(kc + lk) * 768 + sg * 256);
            asm volatile("cp.async.commit_group;");
        }

        #pragma unroll
        for (int k = 0; k < 16; k++) {
            float4 av = *(float4*)&As[s][k][mrow];
            u64 ad0, ad1, ad2, ad3;
            PACKDUP(ad0, av.x); PACKDUP(ad1, av.y); PACKDUP(ad2, av.z); PACKDUP(ad3, av.w);
            #pragma unroll
            for (int sg = 0; sg < 3; sg++) {
                ulonglong2 bq = *(ulonglong2*)&Bs[s][k][sg * 64 + nc0];
                FMA2(acc[0][sg][0], ad0, bq.x); FMA2(acc[0][sg][1], ad0, bq.y);
                FMA2(acc[1][sg][0], ad1, bq.x); FMA2(acc[1][sg][1], ad1, bq.y);
                FMA2(acc[2][sg][0], ad2, bq.x); FMA2(acc[2][sg][1], ad2, bq.y);
                FMA2(acc[3][sg][0], ad3, bq.x); FMA2(acc[3][sg][1], ad3, bq.y);
            }
        }
        s++; if (s >= 3) s = 0;
    }

    // epilogue: GRU on 4 rows x 4 cols
    int r0 = row0 + mrow;
    int cc = g * 64 + nc0;
    float4 dg4 = *(const float4*)(deg + r0);
    float dgs[4] = {dg4.x, dg4.y, dg4.z, dg4.w};

    float ir[4][4], iz[4][4], in4[4][4];   // [row][col]
    #pragma unroll
    for (int i = 0; i < 4; i++) {
        UNPACK2(ir[i][0],  ir[i][1],  acc[i][0][0]); UNPACK2(ir[i][2],  ir[i][3],  acc[i][0][1]);
        UNPACK2(iz[i][0],  iz[i][1],  acc[i][1][0]); UNPACK2(iz[i][2],  iz[i][3],  acc[i][1][1]);
        UNPACK2(in4[i][0], in4[i][1], acc[i][2][0]); UNPACK2(in4[i][2], in4[i][3], acc[i][2][1]);
    }

    #pragma unroll
    for (int j = 0; j < 4; j++) {
        int c = cc + j;
        float bR = bih[c],       cR = bc[c];
        float bZ = bih[c + 256], cZ = bc[c + 256];
        float bNn = bih[c + 512], cNn = bc[c + 512];
        float4 hr = *(const float4*)(ghT + (size_t)c * BN + r0);
        float4 hz = *(const float4*)(ghT + (size_t)(c + 256) * BN + r0);
        float4 hn = *(const float4*)(ghT + (size_t)(c + 512) * BN + r0);
        float4 hv = *(const float4*)(hT + (size_t)c * BN + r0);
        float hrA[4] = {hr.x, hr.y, hr.z, hr.w};
        float hzA[4] = {hz.x, hz.y, hz.z, hz.w};
        float hnA[4] = {hn.x, hn.y, hn.z, hn.w};
        float hvA[4] = {hv.x, hv.y, hv.z, hv.w};
        float hoA[4];
        #pragma unroll
        for (int i = 0; i < 4; i++) {
            float irv = ir[i][j]  + bR  + dgs[i] * cR;
            float izv = iz[i][j]  + bZ  + dgs[i] * cZ;
            float inv = in4[i][j] + bNn + dgs[i] * cNn;
            float rr = 1.f / (1.f + __expf(-(irv + hrA[i])));
            float zz = 1.f / (1.f + __expf(-(izv + hzA[i])));
            float nn = tanhf(inv + rr * hnA[i]);
            hoA[i] = (1.f - zz) * nn + zz * hvA[i];
        }
        float4 ho = {hoA[0], hoA[1], hoA[2], hoA[3]};
        *(float4*)(hT + (size_t)c * BN + r0) = ho;
    }
}

// ---------------- prep: transposes + Wcat/bcat + bc ---------------------------
__global__ void prep(const float* __restrict__ X, const float* __restrict__ msgW2,
                     const float* __restrict__ msgW1, const float* __restrict__ Whh,
                     const float* __restrict__ msgb1, const float* __restrict__ bhh,
                     const float* __restrict__ msgb2, const float* __restrict__ Wih,
                     float* __restrict__ XT, float* __restrict__ M2T,
                     float* __restrict__ Wcat, float* __restrict__ bcat,
                     float* __restrict__ bc)
{
    int blk = blockIdx.x, t = threadIdx.x;
    if (blk < 256) {                     // XT[k][m] = X[m][k]
        int i = blk * 256 + t;
        int k = i >> 10, m = i & 1023;
        XT[i] = X[(size_t)m * Fn + k];
    } else if (blk < 512) {              // M2T[k][m] = msg_W2[m][k]
        int i = (blk - 256) * 256 + t;
        int k = i >> 8, m = i & 255;
        M2T[i] = msgW2[(size_t)m * Hn + k];
    } else if (blk < 1792) {             // Wcat[k][n]
        int i = (blk - 512) * 256 + t;
        int k = i / NC, n = i % NC;
        float v;
        if (n < 256)      v = msgW1[(size_t)k * Hn + n];
        else if (n < 512) v = msgW1[(size_t)(256 + k) * Hn + (n - 256)];
        else              v = Whh[(size_t)k * 768 + (n - 512)];
        Wcat[i] = v;
        if (i < NC)
            bcat[i] = i < 256 ? msgb1[i] : (i < 512 ? 0.f : bhh[i - 512]);
    } else {                             // bc = msg_b2 @ gru_Wih (warp/output)
        int warp = (blk - 1792) * 8 + (t >> 5);
        int lane = t & 31;
        float s = 0.f;
        for (int k = lane; k < Hn; k += 32)
            s += msgb2[k] * Wih[(size_t)k * 768 + warp];
        #pragma unroll
        for (int o = 16; o; o >>= 1) s += __shfl_xor_sync(0xffffffffu, s, o);
        if (lane == 0) bc[warp] = s;
    }
}

// ---------------- E-aggregation -----------------------------------------------
#define IT 8
__global__ void eagg(const float* __restrict__ big2, const int* __restrict__ adj,
                     float* __restrict__ aT, float* __restrict__ deg)
{
    int b  = blockIdx.y;
    int i0 = blockIdx.x * IT;
    int h  = threadIdx.x;

    __shared__ float adjf[Nn][IT];

    float hir[IT], acc[IT];
    #pragma unroll
    for (int t = 0; t < IT; t++) {
        adjf[h][t] = (float)adj[((size_t)(b * Nn + i0 + t)) * Nn + h];
        hir[t] = big2[((size_t)(b * Nn + i0 + t)) * 512 + h];
        acc[t] = 0.f;
    }
    __syncthreads();

    const float* hjb = big2 + (size_t)b * Nn * 512 + 256;
    #pragma unroll 2
    for (int j = 0; j < Nn; j++) {
        float hjv = hjb[(size_t)j * 512 + h];
        float4 a04 = *(float4*)&adjf[j][0];
        float4 a47 = *(float4*)&adjf[j][4];
        acc[0] += a04.x * fmaxf(hir[0] + hjv, 0.f);
        acc[1] += a04.y * fmaxf(hir[1] + hjv, 0.f);
        acc[2] += a04.z * fmaxf(hir[2] + hjv, 0.f);
        acc[3] += a04.w * fmaxf(hir[3] + hjv, 0.f);
        acc[4] += a47.x * fmaxf(hir[4] + hjv, 0.f);
        acc[5] += a47.y * fmaxf(hir[5] + hjv, 0.f);
        acc[6] += a47.z * fmaxf(hir[6] + hjv, 0.f);
        acc[7] += a47.w * fmaxf(hir[7] + hjv, 0.f);
    }

    #pragma unroll
    for (int t = 0; t < IT; t++)
        aT[(size_t)h * BN + b * Nn + i0 + t] = acc[t];

    if (h < IT) {
        float s = 0.f;
        for (int j = 0; j < Nn; j++) s += adjf[j][h];
        deg[b * Nn + i0 + h] = s;
    }
}

// ---------------- readout ------------------------------------------------------
__global__ void readout(const float* __restrict__ hT,
                        const float* __restrict__ W1, const float* __restrict__ b1,
                        const float* __restrict__ W2, const float* __restrict__ b2,
                        float* __restrict__ out)
{
    __shared__ float gsh[Hn];
    __shared__ float hsh[Hn];
    int b = blockIdx.x, t = threadIdx.x;

    float s = 0.f;
    const float* hrow = hT + (size_t)t * BN + b * Nn;
    #pragma unroll 4
    for (int i = 0; i < Nn; i++) s += hrow[i];
    gsh[t] = s;
    __syncthreads();

    float s2 = b1[t];
    for (int k = 0; k < Hn; k++) s2 += gsh[k] * W1[(size_t)k * Hn + t];
    hsh[t] = fmaxf(s2, 0.f);
    __syncthreads();

    if (t < An) {
        float s3 = b2[t];
        for (int k = 0; k < Hn; k++) s3 += hsh[k] * W2[(size_t)k * An + t];
        out[b * An + t] = s3;
    }
}

// ---------------- host launch ---------------------------------------------------
extern "C" void kernel_launch(void* const* d_in, const int* in_sizes, int n_in,
                              void* d_out, int out_size)
{
    const float* X       = (const float*)d_in[0];
    const int*   adj     = (const int*)  d_in[1];
    const float* pre_W1  = (const float*)d_in[2];
    const float* pre_b1  = (const float*)d_in[3];
    const float* pre_W2  = (const float*)d_in[4];
    const float* pre_b2  = (const float*)d_in[5];
    const float* msg_W1  = (const float*)d_in[6];
    const float* msg_b1  = (const float*)d_in[7];
    const float* msg_W2  = (const float*)d_in[8];
    const float* msg_b2  = (const float*)d_in[9];
    const float* gru_Wih = (const float*)d_in[10];
    const float* gru_Whh = (const float*)d_in[11];
    const float* gru_bih = (const float*)d_in[12];
    const float* gru_bhh = (const float*)d_in[13];
    const float* ro_W1   = (const float*)d_in[14];
    const float* ro_b1   = (const float*)d_in[15];
    const float* ro_W2   = (const float*)d_in[16];
    const float* ro_b2   = (const float*)d_in[17];

    float *XT,*tT,*hT,*aT,*M2T,*big2,*ghT,*deg,*Wc,*bc,*Wcat,*bcat;
    cudaGetSymbolAddress((void**)&XT,  d_XT);
    cudaGetSymbolAddress((void**)&tT,  d_tT);
    cudaGetSymbolAddress((void**)&hT,  d_hT);
    cudaGetSymbolAddress((void**)&aT,  d_aT);
    cudaGetSymbolAddress((void**)&M2T, d_M2T);
    cudaGetSymbolAddress((void**)&big2,d_big2);
    cudaGetSymbolAddress((void**)&ghT, d_ghT);
    cudaGetSymbolAddress((void**)&deg, d_deg);
    cudaGetSymbolAddress((void**)&Wc,  d_Wc);
    cudaGetSymbolAddress((void**)&bc,  d_bc);
    cudaGetSymbolAddress((void**)&Wcat,d_Wcat);
    cudaGetSymbolAddress((void**)&bcat,d_bcat);

    cudaFuncSetAttribute(gemmT, cudaFuncAttributeMaxDynamicSharedMemorySize, GEMM_SMEM);
    cudaFuncSetAttribute(gigru, cudaFuncAttributeMaxDynamicSharedMemorySize, GG_SMEM);

    // prep: XT, M2T, Wcat, bcat, bc   (1792 + 96 blocks)
    prep<<<1888, 256>>>(X, msg_W2, msg_W1, gru_Whh, msg_b1, gru_bhh, msg_b2, gru_Wih,
                        XT, M2T, Wcat, bcat, bc);

    // Wc = msg_W2 @ gru_Wih (row-major out)
    gemmT<<<dim3(12, 4), 128, GEMM_SMEM>>>(M2T, Hn, gru_Wih, 768, Hn,
                                           nullptr, Wc, 768, 768, nullptr, 0, 0);

    // pre-MLP: tT = relu(X@W1+b1)^T ; hT = (t@W2+b2)^T
    gemmT<<<dim3(4, 16), 128, GEMM_SMEM>>>(XT, BN, pre_W1, Hn, Fn,
                                           pre_b1, nullptr, 0, 0, tT, BN, 1);
    gemmT<<<dim3(4, 16), 128, GEMM_SMEM>>>(tT, BN, pre_W2, Hn, Hn,
                                           pre_b2, nullptr, 0, 0, hT, BN, 0);

    for (int it = 0; it < Tn; it++) {
        // [hi+b1 | hj] -> big2, gh+bhh -> ghT
        gemmT<<<dim3(20, 16), 128, GEMM_SMEM>>>(hT, BN, Wcat, NC, Hn,
                                                bcat, big2, 512, 512, ghT, BN, 0);
        eagg<<<dim3(Nn / IT, Bn), 256>>>(big2, adj, aT, deg);
        // gi GEMM + GRU fused -> hT
        gigru<<<dim3(4, 16), 256, GG_SMEM>>>(aT, Wc, gru_bih, bc, deg, ghT, hT);
    }

    readout<<<Bn, 256>>>(hT, ro_W1, ro_b1, ro_W2, ro_b2, (float*)d_out);
}